// round 12
// baseline (speedup 1.0000x reference)
#include <cuda_runtime.h>

#define H 512
#define W 512
#define B 64
#define RB 32
#define NSTRIPS (H / RB)   // 16
#define NT 128
#define NBLK (B * NSTRIPS) // 1024

typedef unsigned long long u64;

__device__ float g_part[NBLK * 3];
__device__ unsigned g_count;   // zero at load; last block resets each launch

// ---------- packed f32x2 helpers ----------
__device__ __forceinline__ u64 padd(u64 a, u64 b) {
    u64 r; asm("add.rn.f32x2 %0, %1, %2;" : "=l"(r) : "l"(a), "l"(b)); return r;
}
__device__ __forceinline__ u64 pmul(u64 a, u64 b) {
    u64 r; asm("mul.rn.f32x2 %0, %1, %2;" : "=l"(r) : "l"(a), "l"(b)); return r;
}
__device__ __forceinline__ u64 pfma(u64 a, u64 b, u64 c) {
    u64 r; asm("fma.rn.f32x2 %0, %1, %2, %3;" : "=l"(r) : "l"(a), "l"(b), "l"(c)); return r;
}
__device__ __forceinline__ u64 pdup(float x) {
    unsigned u = __float_as_uint(x);
    return ((u64)u << 32) | (u64)u;
}
#define NEG1_C 0xBF800000BF800000ULL
__device__ __forceinline__ u64 psub(u64 a, u64 b) { return pfma(b, (u64)NEG1_C, a); }
__device__ __forceinline__ u64 pabs(u64 a) { return a & 0x7FFFFFFF7FFFFFFFULL; }
__device__ __forceinline__ float plo(u64 a) { return __uint_as_float((unsigned)a); }
__device__ __forceinline__ float phi(u64 a) { return __uint_as_float((unsigned)(a >> 32)); }
__device__ __forceinline__ u64 ppack(float lo, float hi) {
    return ((u64)__float_as_uint(hi) << 32) | (u64)__float_as_uint(lo);
}

struct Row { u64 a, b; };      // a = cols (4t,4t+1), b = cols (4t+2,4t+3)
struct FRow { Row ud, us, vd, vs; };   // d = t-p, s = t+p for u,v planes

__device__ __forceinline__ Row ldrow(const float* __restrict__ rowbase, int t) {
    ulonglong2 q = *(reinterpret_cast<const ulonglong2*>(rowbase) + t);
    Row r; r.a = q.x; r.b = q.y; return r;
}

// Load one row of all 4 tensors (4x LDG.128) and convert to d/s fields.
__device__ __forceinline__ FRow ldconv(const float* __restrict__ pu,
                                       const float* __restrict__ pv,
                                       const float* __restrict__ tu,
                                       const float* __restrict__ tv,
                                       int y, int t) {
    const size_t off = (size_t)y * W;
    Row qpu = ldrow(pu + off, t);
    Row qpv = ldrow(pv + off, t);
    Row qtu = ldrow(tu + off, t);
    Row qtv = ldrow(tv + off, t);
    FRow f;
    f.ud.a = psub(qtu.a, qpu.a); f.ud.b = psub(qtu.b, qpu.b);
    f.us.a = padd(qtu.a, qpu.a); f.us.b = padd(qtu.b, qpu.b);
    f.vd.a = psub(qtv.a, qpv.a); f.vd.b = psub(qtv.b, qpv.b);
    f.vs.a = padd(qtv.a, qpv.a); f.vs.b = padd(qtv.b, qpv.b);
    return f;
}

// Column-shifted pairs for the (d,s) fields of one plane:
// Ad=(c[-1],c0) Bd=(c1,c2) Cd=(c3,c[+4]) of d; same for s.
// One fused predicated seam (2 scalar LDGs: pred + trut), converted to d/s.
__device__ __forceinline__ void shifts_ds(Row cd, Row cs,
                                          const float* __restrict__ pRow,
                                          const float* __restrict__ tRow,
                                          int tid, int lane,
                                          u64& Ad, u64& Bd, u64& Cd,
                                          u64& As, u64& Bs, u64& Cs) {
    float c0d = plo(cd.a), c1d = phi(cd.a), c2d = plo(cd.b), c3d = phi(cd.b);
    float c0s = plo(cs.a), c1s = phi(cs.a), c2s = plo(cs.b), c3s = phi(cs.b);
    bool pl = (lane == 0)  && (tid > 0);
    bool pr = (lane == 31) && (tid < NT - 1);
    float sd = 0.0f, ss = 0.0f;
    if (pl | pr) {
        int off = pl ? (4 * tid - 1) : (4 * tid + 4);
        float vp = __ldg(pRow + off);
        float vt = __ldg(tRow + off);
        sd = vt - vp;
        ss = vt + vp;
    }
    const unsigned FULL = 0xFFFFFFFFu;
    float vLd = __shfl_up_sync(FULL, c3d, 1);
    float vLs = __shfl_up_sync(FULL, c3s, 1);
    float vRd = __shfl_down_sync(FULL, c0d, 1);
    float vRs = __shfl_down_sync(FULL, c0s, 1);
    if (pl) { vLd = sd; vLs = ss; }
    if (pr) { vRd = sd; vRs = ss; }
    Ad = ppack(vLd, c0d); Bd = ppack(c1d, c2d); Cd = ppack(c3d, vRd);
    As = ppack(vLs, c0s); Bs = ppack(c1s, c2s); Cs = ppack(c3s, vRs);
}

// Fused residual-difference stencil for one 2-col slot.
// mass_raw -> *0.5 at finalize; mom_raw -> *0.125 at finalize.
// Identity: res_t - res_p over bilinear terms = f(d = t-p, s = t+p).
__device__ __forceinline__ void slot_ds(
    u64 umd, u64 ums, u64 uld, u64 uls, u64 urd, u64 urs,
    u64 ubd, u64 ubs, u64 utd, u64 uts,
    u64 vmd, u64 vms, u64 vld, u64 vls, u64 vrd, u64 vrs,
    u64 vbd, u64 vbs, u64 vtd, u64 vts,
    u64 NEG8, u64 N8IRE,
    u64& accM, u64& accO)
{
    u64 P6d = padd(urd, umd), P6s = padd(urs, ums);   // ur+um
    u64 P8d = padd(uld, umd), P8s = padd(uls, ums);   // ul+um
    u64 P1d = padd(utd, umd), P1s = padd(uts, ums);   // ut+um
    u64 P3d = padd(ubd, umd), P3s = padd(ubs, ums);   // ub+um
    u64 P2d = padd(vtd, vmd), P2s = padd(vts, vms);   // vt+vm
    u64 P4d = padd(vbd, vmd), P4s = padd(vbs, vms);   // vb+vm
    u64 P5d = padd(vrd, vmd), P5s = padd(vrs, vms);   // vr+vm
    u64 P7d = padd(vld, vmd), P7s = padd(vls, vms);   // vl+vm

    // mass diff (raw): (ur_d - ul_d) + (vt_d - vb_d)
    u64 mass = padd(psub(P6d, P8d), psub(P2d, P4d));
    accM = padd(accM, pabs(mass));

    // mom_u diff * 8: 2(P6d P6s - P8d P8s) + (P1d P2s + P1s P2d - P3d P4s - P3s P4d)
    //                 - 8*IRE*(P6d+P8d+P1d+P3d - 8 um_d)
    u64 A  = psub(pmul(P6d, P6s), pmul(P8d, P8s));
    u64 cr = psub(pfma(P1s, P2d, pmul(P1d, P2s)),
                  pfma(P3s, P4d, pmul(P3d, P4s)));
    u64 Xu = padd(padd(A, A), cr);
    u64 lu = pfma(umd, NEG8, padd(padd(P6d, P8d), padd(P1d, P3d)));
    u64 momu = pfma(lu, N8IRE, Xu);

    // mom_v diff * 8
    u64 Av  = psub(pmul(P2d, P2s), pmul(P4d, P4s));
    u64 crv = psub(pfma(P5s, P6d, pmul(P5d, P6s)),
                   pfma(P7s, P8d, pmul(P7d, P8s)));
    u64 Xv = padd(padd(Av, Av), crv);
    u64 lv = pfma(vmd, NEG8, padd(padd(P5d, P7d), padd(P2d, P4d)));
    u64 momv = pfma(lv, N8IRE, Xv);

    accO = padd(accO, padd(pabs(momu), pabs(momv)));
}

__global__ __launch_bounds__(NT) void loss_kernel(const float* __restrict__ pred,
                                                  const float* __restrict__ trut,
                                                  float* __restrict__ out)
{
    const int bx = blockIdx.x;
    const int img = bx >> 4;               // / NSTRIPS
    const int strip = bx & (NSTRIPS - 1);
    const int y0 = strip * RB;
    const int tid = threadIdx.x;
    const int lane = tid & 31;

    const size_t HW = (size_t)H * W;
    const float* __restrict__ pu = pred + (size_t)img * 2 * HW;
    const float* __restrict__ pv = pu + HW;
    const float* __restrict__ tu = trut + (size_t)img * 2 * HW;
    const float* __restrict__ tv = tu + HW;

    const u64 NEG8  = pdup(-8.0f);
    const u64 N8IRE = pdup(-8.0f * (1.0f / 400.0f));   // -0.02

    FRow prev = {};
    if (y0 > 0) prev = ldconv(pu, pv, tu, tv, y0 - 1, tid);
    FRow cur  = ldconv(pu, pv, tu, tv, y0, tid);
    FRow next = ldconv(pu, pv, tu, tv, y0 + 1, tid);

    u64 accM0 = 0, accM1 = 0, accO0 = 0, accO1 = 0, accL0 = 0, accL1 = 0;

    #pragma unroll 1
    for (int r = 0; r < RB; ++r) {
        const int y = y0 + r;

        // prefetch row y+2 at the top (consumed as 'next' at iteration r+1)
        FRow buf = {};
        const int yn = y + 2;
        if (r < RB - 1 && yn < H) buf = ldconv(pu, pv, tu, tv, yn, tid);

        // L1 on all points: |t-p| both channels
        accL0 = padd(accL0, padd(pabs(cur.ud.a), pabs(cur.vd.a)));
        accL1 = padd(accL1, padd(pabs(cur.ud.b), pabs(cur.vd.b)));

        if (y >= 1 && y <= H - 2) {
            const size_t roff = (size_t)y * W;
            u64 uAd, uBd, uCd, uAs, uBs, uCs;
            u64 vAd, vBd, vCd, vAs, vBs, vCs;
            shifts_ds(cur.ud, cur.us, pu + roff, tu + roff, tid, lane,
                      uAd, uBd, uCd, uAs, uBs, uCs);
            shifts_ds(cur.vd, cur.vs, pv + roff, tv + roff, tid, lane,
                      vAd, vBd, vCd, vAs, vBs, vCs);

            // slot a: col-neighbors b=A, t=B; row-neighbors l=prev, r=next
            slot_ds(cur.ud.a, cur.us.a, prev.ud.a, prev.us.a, next.ud.a, next.us.a,
                    uAd, uAs, uBd, uBs,
                    cur.vd.a, cur.vs.a, prev.vd.a, prev.vs.a, next.vd.a, next.vs.a,
                    vAd, vAs, vBd, vBs,
                    NEG8, N8IRE, accM0, accO0);
            // slot b: col-neighbors b=B, t=C
            slot_ds(cur.ud.b, cur.us.b, prev.ud.b, prev.us.b, next.ud.b, next.us.b,
                    uBd, uBs, uCd, uCs,
                    cur.vd.b, cur.vs.b, prev.vd.b, prev.vs.b, next.vd.b, next.vs.b,
                    vBd, vBs, vCd, vCs,
                    NEG8, N8IRE, accM1, accO1);
        }

        // rotate sliding window
        prev = cur; cur = next; next = buf;
    }

    // mask boundary columns 0 (lo of slot a, tid 0) and 511 (hi of slot b, tid NT-1)
    if (tid == 0)      { accM0 &= 0xFFFFFFFF00000000ULL; accO0 &= 0xFFFFFFFF00000000ULL; }
    if (tid == NT - 1) { accM1 &= 0x00000000FFFFFFFFULL; accO1 &= 0x00000000FFFFFFFFULL; }

    float sM = plo(accM0) + phi(accM0) + plo(accM1) + phi(accM1);
    float sO = plo(accO0) + phi(accO0) + plo(accO1) + phi(accO1);
    float sL = plo(accL0) + phi(accL0) + plo(accL1) + phi(accL1);

    // block reduce (4 warps)
    const unsigned FULL = 0xFFFFFFFFu;
    #pragma unroll
    for (int off = 16; off > 0; off >>= 1) {
        sM += __shfl_down_sync(FULL, sM, off);
        sO += __shfl_down_sync(FULL, sO, off);
        sL += __shfl_down_sync(FULL, sL, off);
    }
    __shared__ float sh[4][3];
    __shared__ int sh_last;
    const int wid = tid >> 5;
    if (lane == 0) { sh[wid][0] = sM; sh[wid][1] = sO; sh[wid][2] = sL; }
    __syncthreads();

    if (tid == 0) {
        float m = sh[0][0] + sh[1][0] + sh[2][0] + sh[3][0];
        float o = sh[0][1] + sh[1][1] + sh[2][1] + sh[3][1];
        float l = sh[0][2] + sh[1][2] + sh[2][2] + sh[3][2];
        g_part[bx * 3 + 0] = m;
        g_part[bx * 3 + 1] = o;
        g_part[bx * 3 + 2] = l;
        __threadfence();
        unsigned pc = atomicAdd(&g_count, 1u);
        sh_last = (pc == (unsigned)(NBLK - 1)) ? 1 : 0;
    }
    __syncthreads();

    // Last-finished block reduces all partials and writes the scalar.
    if (sh_last) {
        __threadfence();
        double dm = 0.0, dO = 0.0, dl = 0.0;
        for (int i = tid; i < NBLK; i += NT) {
            dm += (double)__ldcg(&g_part[i * 3 + 0]);
            dO += (double)__ldcg(&g_part[i * 3 + 1]);
            dl += (double)__ldcg(&g_part[i * 3 + 2]);
        }
        #pragma unroll
        for (int off = 16; off > 0; off >>= 1) {
            dm += __shfl_down_sync(FULL, dm, off);
            dO += __shfl_down_sync(FULL, dO, off);
            dl += __shfl_down_sync(FULL, dl, off);
        }
        __shared__ double shd[4][3];
        if (lane == 0) { shd[wid][0] = dm; shd[wid][1] = dO; shd[wid][2] = dl; }
        __syncthreads();
        if (tid == 0) {
            double m = shd[0][0] + shd[1][0] + shd[2][0] + shd[3][0];
            double o = shd[0][1] + shd[1][1] + shd[2][1] + shd[3][1];
            double l = shd[0][2] + shd[1][2] + shd[2][2] + shd[3][2];
            const double NM = (double)B * (H - 2) * (W - 2);
            const double NL = (double)B * 2.0 * H * W;
            double lossMass = 0.5   * m / NM;
            double lossMom  = 0.125 * o / NM;
            double lossL1   = l / NL;
            out[0] = (float)((lossMass * 5.0 + lossMom * 25.0 + lossL1) / 3.0);
            g_count = 0;   // reset for next graph replay
        }
    }
}

extern "C" void kernel_launch(void* const* d_in, const int* in_sizes, int n_in,
                              void* d_out, int out_size) {
    const float* pred = (const float*)d_in[0];
    const float* trut = (const float*)d_in[1];
    float* out = (float*)d_out;
    loss_kernel<<<NBLK, NT>>>(pred, trut, out);
}

// round 13
// speedup vs baseline: 1.5509x; 1.5509x over previous
#include <cuda_runtime.h>

#define H 512
#define W 512
#define B 64
#define RB 16
#define NSTRIPS (H / RB)   // 32
#define NT 128

typedef unsigned long long u64;

__device__ double g_sums[3];   // [0]=mass_raw, [1]=mom_raw, [2]=l1

__global__ void init_sums_kernel() {
    if (threadIdx.x < 3) g_sums[threadIdx.x] = 0.0;
}

// ---------- packed f32x2 helpers ----------
__device__ __forceinline__ u64 padd(u64 a, u64 b) {
    u64 r; asm("add.rn.f32x2 %0, %1, %2;" : "=l"(r) : "l"(a), "l"(b)); return r;
}
__device__ __forceinline__ u64 pmul(u64 a, u64 b) {
    u64 r; asm("mul.rn.f32x2 %0, %1, %2;" : "=l"(r) : "l"(a), "l"(b)); return r;
}
__device__ __forceinline__ u64 pfma(u64 a, u64 b, u64 c) {
    u64 r; asm("fma.rn.f32x2 %0, %1, %2, %3;" : "=l"(r) : "l"(a), "l"(b), "l"(c)); return r;
}
__device__ __forceinline__ u64 pdup(float x) {
    unsigned u = __float_as_uint(x);
    return ((u64)u << 32) | (u64)u;
}
#define NEG1_C 0xBF800000BF800000ULL   // (-1.0f, -1.0f)
__device__ __forceinline__ u64 psub(u64 a, u64 b) {   // a - b
    return pfma(b, (u64)NEG1_C, a);
}
__device__ __forceinline__ u64 pabs(u64 a) { return a & 0x7FFFFFFF7FFFFFFFULL; }
__device__ __forceinline__ float plo(u64 a) { return __uint_as_float((unsigned)a); }
__device__ __forceinline__ float phi(u64 a) { return __uint_as_float((unsigned)(a >> 32)); }
__device__ __forceinline__ u64 ppack(float lo, float hi) {
    return ((u64)__float_as_uint(hi) << 32) | (u64)__float_as_uint(lo);
}

struct Row { u64 a, b; };   // a = cols (4t,4t+1), b = cols (4t+2,4t+3)

__device__ __forceinline__ Row ldrow(const float* __restrict__ rowbase, int t) {
    ulonglong2 q = *(reinterpret_cast<const ulonglong2*>(rowbase) + t);
    Row r; r.a = q.x; r.b = q.y; return r;
}

// shifted column pairs for one plane's cur row:
// A=(c[-1],c0)  Bp=(c1,c2)  Cp=(c3,c[+4])
__device__ __forceinline__ void shifts(Row c, const float* __restrict__ rowbase,
                                       int tid, int lane, u64& A, u64& Bp, u64& Cp) {
    float c0 = plo(c.a), c1 = phi(c.a), c2 = plo(c.b), c3 = phi(c.b);
    float vL = __shfl_up_sync(0xFFFFFFFFu, c3, 1);
    float vR = __shfl_down_sync(0xFFFFFFFFu, c0, 1);
    if (lane == 0 && tid > 0)       vL = rowbase[4 * tid - 1];
    if (lane == 31 && tid < NT - 1) vR = rowbase[4 * tid + 4];
    A  = ppack(vL, c0);
    Bp = ppack(c1, c2);
    Cp = ppack(c3, vR);
}

// Raw (unscaled) residuals for 2 columns.
// mass_raw = (ur-ul)+(vt-vb)                        -> *0.5  at finalize
// momu_raw = (du2+duv) - 4*IRE*(ur+ul+ut+ub-4um)    -> *0.25 at finalize
__device__ __forceinline__ void resid_slot(
    u64 um, u64 ul, u64 ur, u64 ub, u64 ut,
    u64 vm, u64 vl, u64 vr, u64 vb, u64 vt,
    u64 TWO, u64 NEG4, u64 N4IRE,
    u64& mass, u64& momu, u64& momv)
{
    u64 t1 = psub(ur, ul);
    u64 t3 = psub(vt, vb);
    mass = padd(t1, t3);

    u64 s1 = padd(ur, ul);
    u64 w1 = pfma(um, TWO, s1);
    u64 du2 = pmul(t1, w1);                 // (ur+um)^2-(ul+um)^2  (raw)
    u64 s3 = padd(vt, vb);
    u64 w3 = pfma(vm, TWO, s3);
    u64 dv2 = pmul(t3, w3);

    u64 p1 = padd(ut, um), p2 = padd(vt, vm);
    u64 p3 = padd(ub, um), p4 = padd(vb, vm);
    u64 duv = psub(pmul(p1, p2), pmul(p3, p4));

    u64 p6 = padd(ur, um), p8 = padd(ul, um);
    u64 p5 = padd(vr, vm), p7 = padd(vl, vm);
    u64 dvu = psub(pmul(p5, p6), pmul(p7, p8));

    u64 Xu = padd(du2, duv);
    u64 Xv = padd(dvu, dv2);

    u64 s5 = padd(ut, ub);
    u64 s6 = padd(s1, s5);
    u64 Yu = pfma(um, NEG4, s6);            // ur+ul+ut+ub-4um
    momu = pfma(Yu, N4IRE, Xu);

    u64 s8 = padd(vr, vl);
    u64 s9 = padd(s3, s8);
    u64 Yv = pfma(vm, NEG4, s9);
    momv = pfma(Yv, N4IRE, Xv);
}

__global__ __launch_bounds__(NT) void loss_kernel(const float* __restrict__ pred,
                                                  const float* __restrict__ trut)
{
    const int bx = blockIdx.x;
    const int img = bx >> 5;               // / NSTRIPS
    const int strip = bx & (NSTRIPS - 1);
    const int y0 = strip * RB;
    const int tid = threadIdx.x;
    const int lane = tid & 31;

    const size_t HW = (size_t)H * W;
    const float* __restrict__ pu = pred + (size_t)img * 2 * HW;
    const float* __restrict__ pv = pu + HW;
    const float* __restrict__ tu = trut + (size_t)img * 2 * HW;
    const float* __restrict__ tv = tu + HW;

    const u64 TWO   = pdup(2.0f);
    const u64 NEG4  = pdup(-4.0f);
    const u64 N4IRE = pdup(-(4.0f * (1.0f / 400.0f)));   // -0.01

    Row uPp = {0, 0}, vPp = {0, 0}, uTp = {0, 0}, vTp = {0, 0};
    if (y0 > 0) {
        uPp = ldrow(pu + (size_t)(y0 - 1) * W, tid);
        vPp = ldrow(pv + (size_t)(y0 - 1) * W, tid);
        uTp = ldrow(tu + (size_t)(y0 - 1) * W, tid);
        vTp = ldrow(tv + (size_t)(y0 - 1) * W, tid);
    }
    Row uPc = ldrow(pu + (size_t)y0 * W, tid);
    Row vPc = ldrow(pv + (size_t)y0 * W, tid);
    Row uTc = ldrow(tu + (size_t)y0 * W, tid);
    Row vTc = ldrow(tv + (size_t)y0 * W, tid);
    Row uPn = ldrow(pu + (size_t)(y0 + 1) * W, tid);
    Row vPn = ldrow(pv + (size_t)(y0 + 1) * W, tid);
    Row uTn = ldrow(tu + (size_t)(y0 + 1) * W, tid);
    Row vTn = ldrow(tv + (size_t)(y0 + 1) * W, tid);

    u64 accM0 = 0, accM1 = 0, accO0 = 0, accO1 = 0, accL0 = 0, accL1 = 0;

    #pragma unroll 4
    for (int r = 0; r < RB; ++r) {
        const int y = y0 + r;

        // prefetch row y+2 (consumed as 'next' at iteration r+1)
        Row nuP = {0, 0}, nvP = {0, 0}, nuT = {0, 0}, nvT = {0, 0};
        const int yn = y + 2;
        if (r < RB - 1 && yn < H) {
            nuP = ldrow(pu + (size_t)yn * W, tid);
            nvP = ldrow(pv + (size_t)yn * W, tid);
            nuT = ldrow(tu + (size_t)yn * W, tid);
            nvT = ldrow(tv + (size_t)yn * W, tid);
        }

        // L1 (all points)
        accL0 = padd(accL0, pabs(psub(uPc.a, uTc.a)));
        accL1 = padd(accL1, pabs(psub(uPc.b, uTc.b)));
        accL0 = padd(accL0, pabs(psub(vPc.a, vTc.a)));
        accL1 = padd(accL1, pabs(psub(vPc.b, vTc.b)));

        if (y >= 1 && y <= H - 2) {
            u64 uA, uB, uC, vA, vB, vC;
            // pred
            shifts(uPc, pu + (size_t)y * W, tid, lane, uA, uB, uC);
            shifts(vPc, pv + (size_t)y * W, tid, lane, vA, vB, vC);
            u64 mP0, oP0, wP0, mP1, oP1, wP1;
            resid_slot(uPc.a, uPp.a, uPn.a, uA, uB,
                       vPc.a, vPp.a, vPn.a, vA, vB,
                       TWO, NEG4, N4IRE, mP0, oP0, wP0);
            resid_slot(uPc.b, uPp.b, uPn.b, uB, uC,
                       vPc.b, vPp.b, vPn.b, vB, vC,
                       TWO, NEG4, N4IRE, mP1, oP1, wP1);
            // trut
            shifts(uTc, tu + (size_t)y * W, tid, lane, uA, uB, uC);
            shifts(vTc, tv + (size_t)y * W, tid, lane, vA, vB, vC);
            u64 mT0, oT0, wT0, mT1, oT1, wT1;
            resid_slot(uTc.a, uTp.a, uTn.a, uA, uB,
                       vTc.a, vTp.a, vTn.a, vA, vB,
                       TWO, NEG4, N4IRE, mT0, oT0, wT0);
            resid_slot(uTc.b, uTp.b, uTn.b, uB, uC,
                       vTc.b, vTp.b, vTn.b, vB, vC,
                       TWO, NEG4, N4IRE, mT1, oT1, wT1);

            accM0 = padd(accM0, pabs(psub(mT0, mP0)));
            accM1 = padd(accM1, pabs(psub(mT1, mP1)));
            accO0 = padd(accO0, padd(pabs(psub(oT0, oP0)), pabs(psub(wT0, wP0))));
            accO1 = padd(accO1, padd(pabs(psub(oT1, oP1)), pabs(psub(wT1, wP1))));
        }

        // rotate sliding window
        uPp = uPc; uPc = uPn; uPn = nuP;
        vPp = vPc; vPc = vPn; vPn = nvP;
        uTp = uTc; uTc = uTn; uTn = nuT;
        vTp = vTc; vTc = vTn; vTn = nvT;
    }

    // mask out boundary columns 0 and 511 (excluded from stencil sums)
    if (tid == 0)      { accM0 &= 0xFFFFFFFF00000000ULL; accO0 &= 0xFFFFFFFF00000000ULL; }
    if (tid == NT - 1) { accM1 &= 0x00000000FFFFFFFFULL; accO1 &= 0x00000000FFFFFFFFULL; }

    float sM = plo(accM0) + phi(accM0) + plo(accM1) + phi(accM1);
    float sO = plo(accO0) + phi(accO0) + plo(accO1) + phi(accO1);
    float sL = plo(accL0) + phi(accL0) + plo(accL1) + phi(accL1);

    // block reduce (4 warps)
    const unsigned FULL = 0xFFFFFFFFu;
    #pragma unroll
    for (int off = 16; off > 0; off >>= 1) {
        sM += __shfl_down_sync(FULL, sM, off);
        sO += __shfl_down_sync(FULL, sO, off);
        sL += __shfl_down_sync(FULL, sL, off);
    }
    __shared__ float sh[4][3];
    const int wid = tid >> 5;
    if (lane == 0) { sh[wid][0] = sM; sh[wid][1] = sO; sh[wid][2] = sL; }
    __syncthreads();
    if (tid == 0) {
        float m = sh[0][0] + sh[1][0] + sh[2][0] + sh[3][0];
        float o = sh[0][1] + sh[1][1] + sh[2][1] + sh[3][1];
        float l = sh[0][2] + sh[1][2] + sh[2][2] + sh[3][2];
        atomicAdd(&g_sums[0], (double)m);
        atomicAdd(&g_sums[1], (double)o);
        atomicAdd(&g_sums[2], (double)l);
    }
}

__global__ void finalize_kernel(float* __restrict__ out) {
    const double NM = (double)B * (H - 2) * (W - 2);   // 64*510*510
    const double NL = (double)B * 2.0 * H * W;         // 64*2*512*512
    double lossMass = 0.5  * g_sums[0] / NM;
    double lossMom  = 0.25 * g_sums[1] / NM;
    double lossL1   = g_sums[2] / NL;
    out[0] = (float)((lossMass * 5.0 + lossMom * 25.0 + lossL1) / 3.0);
}

extern "C" void kernel_launch(void* const* d_in, const int* in_sizes, int n_in,
                              void* d_out, int out_size) {
    const float* pred = (const float*)d_in[0];
    const float* trut = (const float*)d_in[1];
    float* out = (float*)d_out;

    init_sums_kernel<<<1, 32>>>();
    loss_kernel<<<B * NSTRIPS, NT>>>(pred, trut);
    finalize_kernel<<<1, 1>>>(out);
}